// round 15
// baseline (speedup 1.0000x reference)
#include <cuda_runtime.h>

#define NNODES 50000
#define NHEADS 8
#define EPS 1e-8f
#define ATT_NORM 2.0f

// Scratch: per-(node, head) running max of nj as float bits (all values >= 0,
// init 0x00000000, so int atomicMax == float max).
__device__ float g_node_max[NNODES * NHEADS];

// Scatter: warp w owns 8 consecutive edges (2KB x_j, 8 front-issued LDG.128
// per lane). shfl_xor(1)+shfl_xor(2) reduces the 16-dim sum-of-squares inside
// each 4-lane group; 8 broadcast shuffles then hand each lane two (edge,head)
// pairs for the sqrt + scatter-atomicMax epilogue.
__global__ void __launch_bounds__(256) scatter_max_kernel(
        const float4* __restrict__ x_j,
        const int* __restrict__ index,
        int E) {
    int lane = threadIdx.x & 31;
    int w = (blockIdx.x * blockDim.x + threadIdx.x) >> 5;
    int ebase = w * 8;
    if (ebase >= E) return;

    int ksel = lane >> 3;
    int h = lane & 7;

    if (ebase + 8 <= E) {
        float4 v[8];
#pragma unroll
        for (int k = 0; k < 8; ++k)
            v[k] = __ldcs(&x_j[(size_t)w * 256 + k * 32 + lane]);
        int nodeA = index[ebase + ksel];
        int nodeB = index[ebase + 4 + ksel];

        float sq[8];
#pragma unroll
        for (int k = 0; k < 8; ++k) {
            float s = v[k].x * v[k].x + v[k].y * v[k].y
                    + v[k].z * v[k].z + v[k].w * v[k].w;
            s += __shfl_xor_sync(0xFFFFFFFFu, s, 1);
            s += __shfl_xor_sync(0xFFFFFFFFu, s, 2);
            sq[k] = s;
        }
        float bc[8];
#pragma unroll
        for (int k = 0; k < 8; ++k)
            bc[k] = __shfl_sync(0xFFFFFFFFu, sq[k], (lane & 7) * 4);
        float ssA = (ksel == 0) ? bc[0] : (ksel == 1) ? bc[1]
                  : (ksel == 2) ? bc[2] : bc[3];
        float ssB = (ksel == 0) ? bc[4] : (ksel == 1) ? bc[5]
                  : (ksel == 2) ? bc[6] : bc[7];

        float njA = sqrtf(ssA) + EPS;
        float njB = sqrtf(ssB) + EPS;
        if ((unsigned)nodeA < NNODES)
            atomicMax((int*)&g_node_max[nodeA * NHEADS + h], __float_as_int(njA));
        if ((unsigned)nodeB < NNODES)
            atomicMax((int*)&g_node_max[nodeB * NHEADS + h], __float_as_int(njB));
    } else {
        // tail: per-(e,h) scalar path
        for (int e = ebase; e < E; ++e) {
            if (lane < 8) {
                const float4* p = &x_j[(size_t)e * 32 + lane * 4];
                float s = 0.0f;
#pragma unroll
                for (int q = 0; q < 4; ++q) {
                    float4 t = p[q];
                    s += t.x * t.x + t.y * t.y + t.z * t.z + t.w * t.w;
                }
                float nj = sqrtf(s) + EPS;
                int node = index[e];
                if ((unsigned)node < NNODES)
                    atomicMax((int*)&g_node_max[node * NHEADS + lane],
                              __float_as_int(nj));
            }
        }
    }
}

// Finalize: same 8-edge layout. All scatter-independent work (x_i loads, norm
// reduction, e_ij/index loads) runs BEFORE cudaGridDependencySynchronize(),
// overlapping with the scatter kernel's tail via PDL. Only the g_node_max
// gather sits after the dependency sync.
__global__ void __launch_bounds__(256) finalize_kernel(
        const float* __restrict__ e_ij,
        const float4* __restrict__ x_i,
        const int* __restrict__ index,
        float* __restrict__ out,
        int E) {
    int lane = threadIdx.x & 31;
    int w = (blockIdx.x * blockDim.x + threadIdx.x) >> 5;
    int ebase = w * 8;
    if (ebase >= E) {
        cudaGridDependencySynchronize();
        return;
    }

    int ksel = lane >> 3;
    int h = lane & 7;

    if (ebase + 8 <= E) {
        // ---- scatter-independent prologue ----
        float4 v[8];
#pragma unroll
        for (int k = 0; k < 8; ++k)
            v[k] = __ldcs(&x_i[(size_t)w * 256 + k * 32 + lane]);
        float evA = __ldcs(&e_ij[(size_t)ebase * 8 + lane]);
        float evB = __ldcs(&e_ij[(size_t)(ebase + 4) * 8 + lane]);
        int nodeA = index[ebase + ksel];
        int nodeB = index[ebase + 4 + ksel];

        float sq[8];
#pragma unroll
        for (int k = 0; k < 8; ++k) {
            float s = v[k].x * v[k].x + v[k].y * v[k].y
                    + v[k].z * v[k].z + v[k].w * v[k].w;
            s += __shfl_xor_sync(0xFFFFFFFFu, s, 1);
            s += __shfl_xor_sync(0xFFFFFFFFu, s, 2);
            sq[k] = s;
        }
        float bc[8];
#pragma unroll
        for (int k = 0; k < 8; ++k)
            bc[k] = __shfl_sync(0xFFFFFFFFu, sq[k], (lane & 7) * 4);
        float ssA = (ksel == 0) ? bc[0] : (ksel == 1) ? bc[1]
                  : (ksel == 2) ? bc[2] : bc[3];
        float ssB = (ksel == 0) ? bc[4] : (ksel == 1) ? bc[5]
                  : (ksel == 2) ? bc[6] : bc[7];
        float niA = sqrtf(ssA) + EPS;
        float niB = sqrtf(ssB) + EPS;

        // ---- wait for scatter's atomics to be globally visible ----
        cudaGridDependencySynchronize();

        float mxA = ((unsigned)nodeA < NNODES) ? g_node_max[nodeA * NHEADS + h] : 0.0f;
        float mxB = ((unsigned)nodeB < NNODES) ? g_node_max[nodeB * NHEADS + h] : 0.0f;

        float dA = ATT_NORM * (niA + (mxA + EPS)) + EPS;
        float rA = __fdividef(evA, dA);
        rA = fminf(10.0f, fmaxf(-10.0f, rA));
        __stcs(&out[(size_t)ebase * 8 + lane], rA);

        float dB = ATT_NORM * (niB + (mxB + EPS)) + EPS;
        float rB = __fdividef(evB, dB);
        rB = fminf(10.0f, fmaxf(-10.0f, rB));
        __stcs(&out[(size_t)(ebase + 4) * 8 + lane], rB);
    } else {
        cudaGridDependencySynchronize();
        // tail: per-(e,h) scalar path
        for (int e = ebase; e < E; ++e) {
            if (lane < 8) {
                const float4* p = &x_i[(size_t)e * 32 + lane * 4];
                float s = 0.0f;
#pragma unroll
                for (int q = 0; q < 4; ++q) {
                    float4 t = p[q];
                    s += t.x * t.x + t.y * t.y + t.z * t.z + t.w * t.w;
                }
                float ni = sqrtf(s) + EPS;
                int node = index[e];
                float mx = ((unsigned)node < NNODES)
                         ? g_node_max[node * NHEADS + lane] : 0.0f;
                float denom = ATT_NORM * (ni + (mx + EPS)) + EPS;
                float r = __fdividef(e_ij[(size_t)e * 8 + lane], denom);
                r = fminf(10.0f, fmaxf(-10.0f, r));
                out[(size_t)e * 8 + lane] = r;
            }
        }
    }
}

extern "C" void kernel_launch(void* const* d_in, const int* in_sizes, int n_in,
                              void* d_out, int out_size) {
    // metadata order: e_ij [E,H] f32, x_i [E,H,D] f32, x_j [E,H,D] f32, index [E] i32
    const float*  e_ij  = (const float*)d_in[0];
    const float4* x_i   = (const float4*)d_in[1];
    const float4* x_j   = (const float4*)d_in[2];
    const int*    index = (const int*)d_in[3];
    float*        out   = (float*)d_out;

    int E = in_sizes[0] / NHEADS;        // 800,000

    void* nm_ptr = nullptr;
    cudaGetSymbolAddress(&nm_ptr, g_node_max);
    cudaMemsetAsync(nm_ptr, 0, sizeof(float) * NNODES * NHEADS, 0);

    const int B = 256;                                   // 8 warps/block
    int warps8 = (E + 7) / 8;
    int blocks8 = (warps8 + (B / 32) - 1) / (B / 32);    // 12500

    scatter_max_kernel<<<blocks8, B>>>(x_j, index, E);

    // Finalize with programmatic dependent launch: prologue (x_i read + norms)
    // overlaps scatter's tail; gather waits at cudaGridDependencySynchronize().
    cudaLaunchAttribute attrs[1];
    attrs[0].id = cudaLaunchAttributeProgrammaticStreamSerialization;
    attrs[0].val.programmaticStreamSerializationAllowed = 1;

    cudaLaunchConfig_t cfg = {};
    cfg.gridDim = dim3(blocks8, 1, 1);
    cfg.blockDim = dim3(B, 1, 1);
    cfg.dynamicSmemBytes = 0;
    cfg.stream = 0;
    cfg.attrs = attrs;
    cfg.numAttrs = 1;

    cudaLaunchKernelEx(&cfg, finalize_kernel, e_ij, x_i, index, out, E);
}